// round 4
// baseline (speedup 1.0000x reference)
#include <cuda_runtime.h>
#include <cuda_bf16.h>
#include <math.h>
#include <stdint.h>

#define MAX_EDGES 320000

// Weight fragments, B-operand layout for mma.m16n8k16 (col-major B), hi/lo split.
// Entry = uint4 {b0_hi, b1_hi, b0_lo, b1_lo} per lane.
#define FRAG_L1 0
#define FRAG_L2 256
#define FRAG_L3 1280
#define FRAG_L4 2304
#define FRAG_TOTAL 6400
__device__ uint4 g_wfrag[FRAG_TOTAL];

// ---------------------------------------------------------------------------
// mma.sync m16n8k16 row.col bf16 -> f32  (compute_103-legal, runs on HMMA)
// ---------------------------------------------------------------------------
__device__ __forceinline__ void mma16816(float* c,
                                         uint32_t a0, uint32_t a1, uint32_t a2, uint32_t a3,
                                         uint32_t b0, uint32_t b1) {
    asm volatile(
        "mma.sync.aligned.m16n8k16.row.col.f32.bf16.bf16.f32 "
        "{%0,%1,%2,%3}, {%4,%5,%6,%7}, {%8,%9}, {%0,%1,%2,%3};"
        : "+f"(c[0]), "+f"(c[1]), "+f"(c[2]), "+f"(c[3])
        : "r"(a0), "r"(a1), "r"(a2), "r"(a3), "r"(b0), "r"(b1));
}

#define RED2(p, a, b)                                                         \
    asm volatile("red.global.add.v2.f32 [%0], {%1,%2};"                       \
                 :: "l"(p), "f"(a), "f"(b) : "memory")

__device__ __forceinline__ uint32_t pack2(float v0, float v1) {
    uint16_t u0 = __bfloat16_as_ushort(__float2bfloat16_rn(v0));
    uint16_t u1 = __bfloat16_as_ushort(__float2bfloat16_rn(v1));
    return (uint32_t)u0 | ((uint32_t)u1 << 16);
}

__device__ __forceinline__ void split2(float v0, float v1, uint32_t& hi, uint32_t& lo) {
    __nv_bfloat16 h0 = __float2bfloat16_rn(v0);
    __nv_bfloat16 h1 = __float2bfloat16_rn(v1);
    float r0 = v0 - __bfloat162float(h0);
    float r1 = v1 - __bfloat162float(h1);
    hi = (uint32_t)__bfloat16_as_ushort(h0) | ((uint32_t)__bfloat16_as_ushort(h1) << 16);
    lo = pack2(r0, r1);
}

__device__ __forceinline__ float silu_act(float x, float act) {
    return __fdividef(x, 1.0f + __expf(-x)) * act;
}

// ---------------------------------------------------------------------------
// Setup kernel: fp32 weights -> fragment-ordered hi/lo bf16 (scales folded)
// ---------------------------------------------------------------------------
__global__ void build_frags(const float* __restrict__ w0, const float* __restrict__ w1,
                            const float* __restrict__ w2, const float* __restrict__ w3)
{
    int idx = blockIdx.x * blockDim.x + threadIdx.x;
    if (idx >= FRAG_TOTAL) return;

    const float* src; int K, N, ktiles, base; float scale;
    if (idx < FRAG_L2)      { base = FRAG_L1; src = w0; K = 8;  N = 64;  ktiles = 1; scale = 0.35355339059327373f; }
    else if (idx < FRAG_L3) { base = FRAG_L2; src = w1; K = 64; N = 64;  ktiles = 4; scale = 0.125f; }
    else if (idx < FRAG_L4) { base = FRAG_L3; src = w2; K = 64; N = 64;  ktiles = 4; scale = 0.125f; }
    else                    { base = FRAG_L4; src = w3; K = 64; N = 256; ktiles = 4; scale = 0.125f; }

    int fid  = idx - base;
    int lane = fid & 31, pair = fid >> 5;
    int kt = pair % ktiles, nt = pair / ktiles;
    int g = lane >> 2, t = lane & 3;
    int n  = nt * 8 + g;
    int kb = kt * 16 + 2 * t;
    int ks[4] = { kb, kb + 1, kb + 8, kb + 9 };

    uint16_t hi[4], lo[4];
#pragma unroll
    for (int i = 0; i < 4; i++) {
        float v = (ks[i] < K) ? src[ks[i] * N + n] * scale : 0.0f;
        __nv_bfloat16 h = __float2bfloat16_rn(v);
        float r = v - __bfloat162float(h);
        hi[i] = __bfloat16_as_ushort(h);
        lo[i] = __bfloat16_as_ushort(__float2bfloat16_rn(r));
    }
    uint4 o;
    o.x = (uint32_t)hi[0] | ((uint32_t)hi[1] << 16);
    o.y = (uint32_t)hi[2] | ((uint32_t)hi[3] << 16);
    o.z = (uint32_t)lo[0] | ((uint32_t)lo[1] << 16);
    o.w = (uint32_t)lo[2] | ((uint32_t)lo[3] << 16);
    g_wfrag[idx] = o;
}

// ---------------------------------------------------------------------------
// Fused kernel helpers
// ---------------------------------------------------------------------------
__device__ __forceinline__ void act_split(const float* acc, uint32_t* ah, uint32_t* al,
                                          float act) {
#pragma unroll
    for (int kt = 0; kt < 4; kt++) {
        const float* T0 = acc + (2 * kt) * 4;
        const float* T1 = acc + (2 * kt + 1) * 4;
        split2(silu_act(T0[0], act), silu_act(T0[1], act), ah[kt * 4 + 0], al[kt * 4 + 0]);
        split2(silu_act(T0[2], act), silu_act(T0[3], act), ah[kt * 4 + 1], al[kt * 4 + 1]);
        split2(silu_act(T1[0], act), silu_act(T1[1], act), ah[kt * 4 + 2], al[kt * 4 + 2]);
        split2(silu_act(T1[2], act), silu_act(T1[3], act), ah[kt * 4 + 3], al[kt * 4 + 3]);
    }
}

#define MIX_STRIDE 66   /* floats per row in the bounce buffer (64 + 2 pad) */

// Layer-4 chunk CHUNK: 12 MMAs -> bounce via smem -> gather+scatter-add.
template <int CHUNK>
__device__ __forceinline__ void process_chunk(
    const uint32_t* ah, const uint32_t* al,
    int lane, int warp, int g, int t,
    float* mixbuf, const int* sh_s, const int* sh_r, const float* sh_ev,
    const float* __restrict__ node_feats, float* __restrict__ out, int cnt)
{
    float acc[32];
#pragma unroll
    for (int i = 0; i < 32; i++) acc[i] = 0.f;
#pragma unroll
    for (int nt = 0; nt < 8; nt++) {
#pragma unroll
        for (int kt = 0; kt < 4; kt++) {
            uint4 f = __ldg(&g_wfrag[FRAG_L4 + ((CHUNK * 8 + nt) * 4 + kt) * 32 + lane]);
            float* c = &acc[nt * 4];
            const uint32_t* A = &ah[kt * 4];
            const uint32_t* L = &al[kt * 4];
            mma16816(c, A[0], A[1], A[2], A[3], f.x, f.y);
            mma16816(c, A[0], A[1], A[2], A[3], f.z, f.w);
            mma16816(c, L[0], L[1], L[2], L[3], f.x, f.y);
        }
    }

    // Bounce this 128x64 mix chunk through smem (double-buffered).
    float* mb = mixbuf + (CHUNK & 1) * (128 * MIX_STRIDE);
    int r0 = warp * 16 + g, r1 = r0 + 8;
#pragma unroll
    for (int nt = 0; nt < 8; nt++) {
        int col = nt * 8 + 2 * t;
        *(float2*)&mb[r0 * MIX_STRIDE + col] = make_float2(acc[nt * 4 + 0], acc[nt * 4 + 1]);
        *(float2*)&mb[r1 * MIX_STRIDE + col] = make_float2(acc[nt * 4 + 2], acc[nt * 4 + 3]);
    }
    __syncthreads();

    const float S   = 0.25f;                    // 1/sqrt(16)
    const float IS3 = 0.57735026918962576f;     // 1/sqrt(3)

    // Each warp scatters 16 edges; lane owns channels m0=2*lane, m1=2*lane+1.
#pragma unroll 1
    for (int i = 0; i < 16; i++) {
        int el = warp * 16 + i;
        if (el >= cnt) break;                   // warp-uniform
        int s = sh_s[el], r = sh_r[el];
        const float* nrow = node_feats + (size_t)s * 256;
        float* orow = out + (size_t)r * 512;
        float2 mx = *(float2*)&mb[el * MIX_STRIDE + 2 * lane];

        if (CHUNK == 0) {
            float2 ms = __ldg((const float2*)(nrow + 2 * lane));
            RED2(orow + 2 * lane, ms.x * mx.x * S, ms.y * mx.y * S);
        } else if (CHUNK == 1) {
            float ev0 = sh_ev[el * 3 + 0], ev1 = sh_ev[el * 3 + 1], ev2 = sh_ev[el * 3 + 2];
            float2 va = __ldg((const float2*)(nrow + 64 + 6 * lane));
            float2 vb = __ldg((const float2*)(nrow + 64 + 6 * lane + 2));
            float2 vc = __ldg((const float2*)(nrow + 64 + 6 * lane + 4));
            float t0 = (va.x * ev0 + va.y * ev1 + vb.x * ev2) * IS3;
            float t1 = (vb.y * ev0 + vc.x * ev1 + vc.y * ev2) * IS3;
            RED2(orow + 64 + 2 * lane, t0 * mx.x * S, t1 * mx.y * S);
        } else if (CHUNK == 2) {
            float2 va = __ldg((const float2*)(nrow + 64 + 6 * lane));
            float2 vb = __ldg((const float2*)(nrow + 64 + 6 * lane + 2));
            float2 vc = __ldg((const float2*)(nrow + 64 + 6 * lane + 4));
            float c0 = mx.x * S, c1 = mx.y * S;
            RED2(orow + 128 + 6 * lane,     va.x * c0, va.y * c0);
            RED2(orow + 128 + 6 * lane + 2, vb.x * c0, vb.y * c1);
            RED2(orow + 128 + 6 * lane + 4, vc.x * c1, vc.y * c1);
        } else {
            float ev0 = sh_ev[el * 3 + 0], ev1 = sh_ev[el * 3 + 1], ev2 = sh_ev[el * 3 + 2];
            float2 ms = __ldg((const float2*)(nrow + 2 * lane));
            float d0 = ms.x * mx.x * S, d1 = ms.y * mx.y * S;
            RED2(orow + 320 + 6 * lane,     ev0 * d0, ev1 * d0);
            RED2(orow + 320 + 6 * lane + 2, ev2 * d0, ev0 * d1);
            RED2(orow + 320 + 6 * lane + 4, ev1 * d1, ev2 * d1);
        }
    }
}

// ---------------------------------------------------------------------------
// Fused kernel: MLP (chained warp MMAs) + message build + scatter-add.
// Block = 256 threads = 8 warps = 128 edges (16 per warp).
// ---------------------------------------------------------------------------
__global__ void __launch_bounds__(256)
fused_kernel(const float* __restrict__ edge_attrs,
             const float* __restrict__ node_feats,
             const int* __restrict__ senders,
             const int* __restrict__ receivers,
             float* __restrict__ out,
             int n_edges, float act)
{
    extern __shared__ float smem[];
    float* mixbuf = smem;                                // 2 * 128 * 66 floats
    int*   sh_s   = (int*)(smem + 2 * 128 * MIX_STRIDE); // 128
    int*   sh_r   = sh_s + 128;                          // 128
    float* sh_ev  = (float*)(sh_r + 128);                // 128 * 3

    int tid = threadIdx.x, lane = tid & 31, warp = tid >> 5;
    int g = lane >> 2, t = lane & 3;
    int base = blockIdx.x * 128;
    int cnt = n_edges - base; if (cnt > 128) cnt = 128;

    if (tid < 128 && tid < cnt) {
        int e = base + tid;
        sh_s[tid] = __ldg(senders + e);
        sh_r[tid] = __ldg(receivers + e);
        const float* ea = edge_attrs + (size_t)e * 11;
        sh_ev[tid * 3 + 0] = __ldg(ea + 8);
        sh_ev[tid * 3 + 1] = __ldg(ea + 9);
        sh_ev[tid * 3 + 2] = __ldg(ea + 10);
    }

    // ---- Layer 1 A fragments from edge_attrs (K=8, cols 8..15 zero) ----
    int row0 = base + warp * 16 + g;
    int row1 = row0 + 8;
    float x00 = 0.f, x01 = 0.f, x10 = 0.f, x11 = 0.f;
    if (row0 < n_edges) {
        const float* p = edge_attrs + (size_t)row0 * 11 + 2 * t;
        x00 = __ldg(p); x01 = __ldg(p + 1);
    }
    if (row1 < n_edges) {
        const float* p = edge_attrs + (size_t)row1 * 11 + 2 * t;
        x10 = __ldg(p); x11 = __ldg(p + 1);
    }
    uint32_t a0h, a0l, a1h, a1l;
    split2(x00, x01, a0h, a0l);
    split2(x10, x11, a1h, a1l);

    float acc[32];
    uint32_t ah[16], al[16];

    // ---- Layer 1: N=64, single k-tile ----
#pragma unroll
    for (int i = 0; i < 32; i++) acc[i] = 0.f;
#pragma unroll
    for (int nt = 0; nt < 8; nt++) {
        uint4 f = __ldg(&g_wfrag[FRAG_L1 + nt * 32 + lane]);
        float* c = &acc[nt * 4];
        mma16816(c, a0h, a1h, 0u, 0u, f.x, f.y);
        mma16816(c, a0h, a1h, 0u, 0u, f.z, f.w);
        mma16816(c, a0l, a1l, 0u, 0u, f.x, f.y);
    }
    act_split(acc, ah, al, act);

    // ---- Layer 2: 64x64 ----
#pragma unroll
    for (int i = 0; i < 32; i++) acc[i] = 0.f;
#pragma unroll
    for (int nt = 0; nt < 8; nt++) {
#pragma unroll
        for (int kt = 0; kt < 4; kt++) {
            uint4 f = __ldg(&g_wfrag[FRAG_L2 + (nt * 4 + kt) * 32 + lane]);
            float* c = &acc[nt * 4];
            const uint32_t* A = &ah[kt * 4];
            const uint32_t* L = &al[kt * 4];
            mma16816(c, A[0], A[1], A[2], A[3], f.x, f.y);
            mma16816(c, A[0], A[1], A[2], A[3], f.z, f.w);
            mma16816(c, L[0], L[1], L[2], L[3], f.x, f.y);
        }
    }
    act_split(acc, ah, al, act);

    // ---- Layer 3: 64x64 ----
#pragma unroll
    for (int i = 0; i < 32; i++) acc[i] = 0.f;
#pragma unroll
    for (int nt = 0; nt < 8; nt++) {
#pragma unroll
        for (int kt = 0; kt < 4; kt++) {
            uint4 f = __ldg(&g_wfrag[FRAG_L3 + (nt * 4 + kt) * 32 + lane]);
            float* c = &acc[nt * 4];
            const uint32_t* A = &ah[kt * 4];
            const uint32_t* L = &al[kt * 4];
            mma16816(c, A[0], A[1], A[2], A[3], f.x, f.y);
            mma16816(c, A[0], A[1], A[2], A[3], f.z, f.w);
            mma16816(c, L[0], L[1], L[2], L[3], f.x, f.y);
        }
    }
    act_split(acc, ah, al, act);

    // ---- Layer 4 chunks fused with scatter (double-buffered bounce) ----
    process_chunk<0>(ah, al, lane, warp, g, t, mixbuf, sh_s, sh_r, sh_ev,
                     node_feats, out, cnt);
    process_chunk<1>(ah, al, lane, warp, g, t, mixbuf, sh_s, sh_r, sh_ev,
                     node_feats, out, cnt);
    process_chunk<2>(ah, al, lane, warp, g, t, mixbuf, sh_s, sh_r, sh_ev,
                     node_feats, out, cnt);
    process_chunk<3>(ah, al, lane, warp, g, t, mixbuf, sh_s, sh_r, sh_ev,
                     node_feats, out, cnt);
}

// ---------------------------------------------------------------------------
// Host
// ---------------------------------------------------------------------------
static float compute_act_cst() {
    const int    N = 20000;
    const double a = -14.0, b = 14.0;
    const double h = (b - a) / N;
    double sum = 0.0;
    for (int i = 0; i <= N; i++) {
        double xx  = a + h * i;
        double sig = 1.0 / (1.0 + exp(-xx));
        double sl  = xx * sig;
        double f   = exp(-0.5 * xx * xx) * sl * sl;
        double wq  = (i == 0 || i == N) ? 1.0 : ((i & 1) ? 4.0 : 2.0);
        sum += wq * f;
    }
    sum *= h / 3.0;
    sum /= sqrt(2.0 * M_PI);
    return (float)(1.0 / sqrt(sum));
}

extern "C" void kernel_launch(void* const* d_in, const int* in_sizes, int n_in,
                              void* d_out, int out_size)
{
    const float* node_feats = (const float*)d_in[0];
    const float* edge_attrs = (const float*)d_in[1];
    const int*   senders    = (const int*)d_in[2];
    const int*   receivers  = (const int*)d_in[3];
    const float* w0         = (const float*)d_in[4];
    const float* w1         = (const float*)d_in[5];
    const float* w2         = (const float*)d_in[6];
    const float* w3         = (const float*)d_in[7];
    float*       out        = (float*)d_out;

    int n_edges = in_sizes[2];
    if (n_edges > MAX_EDGES) n_edges = MAX_EDGES;

    float act = compute_act_cst();

    cudaMemsetAsync(d_out, 0, (size_t)out_size * sizeof(float));

    build_frags<<<(FRAG_TOTAL + 255) / 256, 256>>>(w0, w1, w2, w3);

    const int smem_bytes = (2 * 128 * MIX_STRIDE) * 4 + 128 * 4 * 2 + 128 * 3 * 4;
    cudaFuncSetAttribute(fused_kernel, cudaFuncAttributeMaxDynamicSharedMemorySize,
                         smem_bytes);
    int blocks = (n_edges + 127) / 128;
    fused_kernel<<<blocks, 256, smem_bytes>>>(edge_attrs, node_feats, senders,
                                              receivers, out, n_edges, act);
}

// round 6
// speedup vs baseline: 1.0104x; 1.0104x over previous
#include <cuda_runtime.h>
#include <cuda_bf16.h>
#include <math.h>
#include <stdint.h>

#define MAX_EDGES 320000

// Weight fragments, B-operand layout for mma.m16n8k16 (col-major B), hi/lo split.
// Entry = uint4 {b0_hi, b1_hi, b0_lo, b1_lo} per lane.
#define FRAG_L1 0
#define FRAG_L2 256
#define FRAG_L3 1280
#define FRAG_L4 2304
#define FRAG_TOTAL 6400
__device__ uint4 g_wfrag[FRAG_TOTAL];

// ---------------------------------------------------------------------------
// mma.sync m16n8k16 row.col bf16 -> f32  (compute_103-legal, runs on HMMA)
// ---------------------------------------------------------------------------
__device__ __forceinline__ void mma16816(float* c,
                                         uint32_t a0, uint32_t a1, uint32_t a2, uint32_t a3,
                                         uint32_t b0, uint32_t b1) {
    asm volatile(
        "mma.sync.aligned.m16n8k16.row.col.f32.bf16.bf16.f32 "
        "{%0,%1,%2,%3}, {%4,%5,%6,%7}, {%8,%9}, {%0,%1,%2,%3};"
        : "+f"(c[0]), "+f"(c[1]), "+f"(c[2]), "+f"(c[3])
        : "r"(a0), "r"(a1), "r"(a2), "r"(a3), "r"(b0), "r"(b1));
}

__device__ __forceinline__ void red4(float* p, float a, float b, float c, float d) {
    asm volatile("red.global.add.v4.f32 [%0], {%1,%2,%3,%4};"
                 :: "l"(p), "f"(a), "f"(b), "f"(c), "f"(d) : "memory");
}

__device__ __forceinline__ uint32_t pack2(float v0, float v1) {
    uint16_t u0 = __bfloat16_as_ushort(__float2bfloat16_rn(v0));
    uint16_t u1 = __bfloat16_as_ushort(__float2bfloat16_rn(v1));
    return (uint32_t)u0 | ((uint32_t)u1 << 16);
}

__device__ __forceinline__ void split2(float v0, float v1, uint32_t& hi, uint32_t& lo) {
    __nv_bfloat16 h0 = __float2bfloat16_rn(v0);
    __nv_bfloat16 h1 = __float2bfloat16_rn(v1);
    float r0 = v0 - __bfloat162float(h0);
    float r1 = v1 - __bfloat162float(h1);
    hi = (uint32_t)__bfloat16_as_ushort(h0) | ((uint32_t)__bfloat16_as_ushort(h1) << 16);
    lo = pack2(r0, r1);
}

__device__ __forceinline__ float silu_act(float x, float act) {
    return __fdividef(x, 1.0f + __expf(-x)) * act;
}

// ---------------------------------------------------------------------------
// Setup: fp32 weights -> fragment-ordered hi/lo bf16 (scales folded).
// L4 columns are PERMUTED so that D-fragment lane t owns 16 consecutive
// output channels: phys = chunk*64 + t*16 + nt_in*2 + j  (t = (n%8)>>1, j = n&1).
// ---------------------------------------------------------------------------
__global__ void build_frags(const float* __restrict__ w0, const float* __restrict__ w1,
                            const float* __restrict__ w2, const float* __restrict__ w3)
{
    int idx = blockIdx.x * blockDim.x + threadIdx.x;
    if (idx >= FRAG_TOTAL) return;

    const float* src; int K, N, ktiles, base; float scale;
    if (idx < FRAG_L2)      { base = FRAG_L1; src = w0; K = 8;  N = 64;  ktiles = 1; scale = 0.35355339059327373f; }
    else if (idx < FRAG_L3) { base = FRAG_L2; src = w1; K = 64; N = 64;  ktiles = 4; scale = 0.125f; }
    else if (idx < FRAG_L4) { base = FRAG_L3; src = w2; K = 64; N = 64;  ktiles = 4; scale = 0.125f; }
    else                    { base = FRAG_L4; src = w3; K = 64; N = 256; ktiles = 4; scale = 0.125f; }

    int fid  = idx - base;
    int lane = fid & 31, pair = fid >> 5;
    int kt = pair % ktiles, nt = pair / ktiles;
    int g = lane >> 2, t = lane & 3;

    int n;
    if (base == FRAG_L4) {
        int chunk = nt >> 3, nt_in = nt & 7;
        n = chunk * 64 + ((g >> 1) << 4) + nt_in * 2 + (g & 1);  // permuted
    } else {
        n = nt * 8 + g;
    }

    int kb = kt * 16 + 2 * t;
    int ks[4] = { kb, kb + 1, kb + 8, kb + 9 };

    uint16_t hi[4], lo[4];
#pragma unroll
    for (int i = 0; i < 4; i++) {
        float v = (ks[i] < K) ? src[ks[i] * N + n] * scale : 0.0f;
        __nv_bfloat16 h = __float2bfloat16_rn(v);
        float r = v - __bfloat162float(h);
        hi[i] = __bfloat16_as_ushort(h);
        lo[i] = __bfloat16_as_ushort(__float2bfloat16_rn(r));
    }
    uint4 o;
    o.x = (uint32_t)hi[0] | ((uint32_t)hi[1] << 16);
    o.y = (uint32_t)hi[2] | ((uint32_t)hi[3] << 16);
    o.z = (uint32_t)lo[0] | ((uint32_t)lo[1] << 16);
    o.w = (uint32_t)lo[2] | ((uint32_t)lo[3] << 16);
    g_wfrag[idx] = o;
}

// ---------------------------------------------------------------------------
// Fused kernel helpers
// ---------------------------------------------------------------------------
__device__ __forceinline__ void act_split(const float* acc, uint32_t* ah, uint32_t* al,
                                          float act) {
#pragma unroll
    for (int kt = 0; kt < 4; kt++) {
        const float* T0 = acc + (2 * kt) * 4;
        const float* T1 = acc + (2 * kt + 1) * 4;
        split2(silu_act(T0[0], act), silu_act(T0[1], act), ah[kt * 4 + 0], al[kt * 4 + 0]);
        split2(silu_act(T0[2], act), silu_act(T0[3], act), ah[kt * 4 + 1], al[kt * 4 + 1]);
        split2(silu_act(T1[0], act), silu_act(T1[1], act), ah[kt * 4 + 2], al[kt * 4 + 2]);
        split2(silu_act(T1[2], act), silu_act(T1[3], act), ah[kt * 4 + 3], al[kt * 4 + 3]);
    }
}

// Scatter one edge's 16 channels (lane-owned, consecutive) for chunk CHUNK.
// sel = 0 for row g, 2 for row g+8. acc[8q+sel(+1)] = channels t*16+4q(+1);
// acc[8q+4+sel(+1)] = channels t*16+4q+2(+3).
template <int CHUNK>
__device__ __forceinline__ void scatter_edge(const float* acc, int sel,
                                             const float* __restrict__ nrow,
                                             float* __restrict__ orow,
                                             float ev0, float ev1, float ev2, int t)
{
    const float S   = 0.25f;                    // 1/sqrt(16)
    const float IS3 = 0.57735026918962576f;     // 1/sqrt(3)
    int b16 = t * 16;
#pragma unroll
    for (int q = 0; q < 4; q++) {
        float m0 = acc[8 * q + sel]     * S;
        float m1 = acc[8 * q + sel + 1] * S;
        float m2 = acc[8 * q + 4 + sel]     * S;
        float m3 = acc[8 * q + 4 + sel + 1] * S;

        if (CHUNK == 0) {
            float4 ms = __ldg((const float4*)(nrow + b16 + 4 * q));
            red4(orow + b16 + 4 * q, ms.x * m0, ms.y * m1, ms.z * m2, ms.w * m3);
        } else if (CHUNK == 1) {
            const float4* vp = (const float4*)(nrow + 64 + 48 * t + 12 * q);
            float4 va = __ldg(vp), vb = __ldg(vp + 1), vc = __ldg(vp + 2);
            float t0 = (va.x * ev0 + va.y * ev1 + va.z * ev2) * IS3;
            float t1 = (va.w * ev0 + vb.x * ev1 + vb.y * ev2) * IS3;
            float t2 = (vb.z * ev0 + vb.w * ev1 + vc.x * ev2) * IS3;
            float t3 = (vc.y * ev0 + vc.z * ev1 + vc.w * ev2) * IS3;
            red4(orow + 64 + b16 + 4 * q, t0 * m0, t1 * m1, t2 * m2, t3 * m3);
        } else if (CHUNK == 2) {
            const float4* vp = (const float4*)(nrow + 64 + 48 * t + 12 * q);
            float4 va = __ldg(vp), vb = __ldg(vp + 1), vc = __ldg(vp + 2);
            float* po = orow + 128 + 48 * t + 12 * q;
            red4(po,     va.x * m0, va.y * m0, va.z * m0, va.w * m1);
            red4(po + 4, vb.x * m1, vb.y * m1, vb.z * m2, vb.w * m2);
            red4(po + 8, vc.x * m2, vc.y * m3, vc.z * m3, vc.w * m3);
        } else {
            float4 ms = __ldg((const float4*)(nrow + b16 + 4 * q));
            float d0 = ms.x * m0, d1 = ms.y * m1, d2 = ms.z * m2, d3 = ms.w * m3;
            float* po = orow + 320 + 48 * t + 12 * q;
            red4(po,     d0 * ev0, d0 * ev1, d0 * ev2, d1 * ev0);
            red4(po + 4, d1 * ev1, d1 * ev2, d2 * ev0, d2 * ev1);
            red4(po + 8, d2 * ev2, d3 * ev0, d3 * ev1, d3 * ev2);
        }
    }
}

// Layer-4 chunk: 12 MMAs then direct per-lane scatter (no smem, no barriers).
template <int CHUNK>
__device__ __forceinline__ void process_chunk(
    const uint32_t* ah, const uint32_t* al, int lane, int t,
    bool valid0, bool valid1,
    const float* __restrict__ nrow0, float* __restrict__ orow0,
    const float* __restrict__ nrow1, float* __restrict__ orow1,
    float e00, float e01, float e02, float e10, float e11, float e12)
{
    float acc[32];
#pragma unroll
    for (int i = 0; i < 32; i++) acc[i] = 0.f;
#pragma unroll
    for (int nt = 0; nt < 8; nt++) {
#pragma unroll
        for (int kt = 0; kt < 4; kt++) {
            uint4 f = __ldg(&g_wfrag[FRAG_L4 + ((CHUNK * 8 + nt) * 4 + kt) * 32 + lane]);
            float* c = &acc[nt * 4];
            const uint32_t* A = &ah[kt * 4];
            const uint32_t* L = &al[kt * 4];
            mma16816(c, A[0], A[1], A[2], A[3], f.x, f.y);
            mma16816(c, A[0], A[1], A[2], A[3], f.z, f.w);
            mma16816(c, L[0], L[1], L[2], L[3], f.x, f.y);
        }
    }
    if (valid0) scatter_edge<CHUNK>(acc, 0, nrow0, orow0, e00, e01, e02, t);
    if (valid1) scatter_edge<CHUNK>(acc, 2, nrow1, orow1, e10, e11, e12, t);
}

// ---------------------------------------------------------------------------
// Fused kernel: MLP (chained warp MMAs) + direct scatter-add.
// Block = 256 threads = 8 warps = 128 edges (16 per warp). No shared memory.
// ---------------------------------------------------------------------------
__global__ void __launch_bounds__(256)
fused_kernel(const float* __restrict__ edge_attrs,
             const float* __restrict__ node_feats,
             const int* __restrict__ senders,
             const int* __restrict__ receivers,
             float* __restrict__ out,
             int n_edges, float act)
{
    int tid = threadIdx.x, lane = tid & 31, warp = tid >> 5;
    int g = lane >> 2, t = lane & 3;
    int wbase = blockIdx.x * 128 + warp * 16;
    int e0 = wbase + g, e1 = e0 + 8;
    bool valid0 = e0 < n_edges, valid1 = e1 < n_edges;

    // Per-edge metadata (redundant across the 4-lane group; L1 broadcasts).
    int s0 = 0, r0 = 0, s1 = 0, r1 = 0;
    float e00 = 0.f, e01 = 0.f, e02 = 0.f, e10 = 0.f, e11 = 0.f, e12 = 0.f;
    if (valid0) {
        s0 = __ldg(senders + e0); r0 = __ldg(receivers + e0);
        const float* ea = edge_attrs + (size_t)e0 * 11;
        e00 = __ldg(ea + 8); e01 = __ldg(ea + 9); e02 = __ldg(ea + 10);
    }
    if (valid1) {
        s1 = __ldg(senders + e1); r1 = __ldg(receivers + e1);
        const float* ea = edge_attrs + (size_t)e1 * 11;
        e10 = __ldg(ea + 8); e11 = __ldg(ea + 9); e12 = __ldg(ea + 10);
    }
    const float* nrow0 = node_feats + (size_t)s0 * 256;
    const float* nrow1 = node_feats + (size_t)s1 * 256;
    float* orow0 = out + (size_t)r0 * 512;
    float* orow1 = out + (size_t)r1 * 512;

    // ---- Layer 1 A fragments from edge_attrs (K=8, cols 8..15 zero) ----
    float x00 = 0.f, x01 = 0.f, x10 = 0.f, x11 = 0.f;
    if (valid0) {
        const float* p = edge_attrs + (size_t)e0 * 11 + 2 * t;
        x00 = __ldg(p); x01 = __ldg(p + 1);
    }
    if (valid1) {
        const float* p = edge_attrs + (size_t)e1 * 11 + 2 * t;
        x10 = __ldg(p); x11 = __ldg(p + 1);
    }
    uint32_t a0h, a0l, a1h, a1l;
    split2(x00, x01, a0h, a0l);
    split2(x10, x11, a1h, a1l);

    float acc[32];
    uint32_t ah[16], al[16];

    // ---- Layer 1: N=64, single k-tile ----
#pragma unroll
    for (int i = 0; i < 32; i++) acc[i] = 0.f;
#pragma unroll
    for (int nt = 0; nt < 8; nt++) {
        uint4 f = __ldg(&g_wfrag[FRAG_L1 + nt * 32 + lane]);
        float* c = &acc[nt * 4];
        mma16816(c, a0h, a1h, 0u, 0u, f.x, f.y);
        mma16816(c, a0h, a1h, 0u, 0u, f.z, f.w);
        mma16816(c, a0l, a1l, 0u, 0u, f.x, f.y);
    }
    act_split(acc, ah, al, act);

    // ---- Layer 2: 64x64 ----
#pragma unroll
    for (int i = 0; i < 32; i++) acc[i] = 0.f;
#pragma unroll
    for (int nt = 0; nt < 8; nt++) {
#pragma unroll
        for (int kt = 0; kt < 4; kt++) {
            uint4 f = __ldg(&g_wfrag[FRAG_L2 + (nt * 4 + kt) * 32 + lane]);
            float* c = &acc[nt * 4];
            const uint32_t* A = &ah[kt * 4];
            const uint32_t* L = &al[kt * 4];
            mma16816(c, A[0], A[1], A[2], A[3], f.x, f.y);
            mma16816(c, A[0], A[1], A[2], A[3], f.z, f.w);
            mma16816(c, L[0], L[1], L[2], L[3], f.x, f.y);
        }
    }
    act_split(acc, ah, al, act);

    // ---- Layer 3: 64x64 ----
#pragma unroll
    for (int i = 0; i < 32; i++) acc[i] = 0.f;
#pragma unroll
    for (int nt = 0; nt < 8; nt++) {
#pragma unroll
        for (int kt = 0; kt < 4; kt++) {
            uint4 f = __ldg(&g_wfrag[FRAG_L3 + (nt * 4 + kt) * 32 + lane]);
            float* c = &acc[nt * 4];
            const uint32_t* A = &ah[kt * 4];
            const uint32_t* L = &al[kt * 4];
            mma16816(c, A[0], A[1], A[2], A[3], f.x, f.y);
            mma16816(c, A[0], A[1], A[2], A[3], f.z, f.w);
            mma16816(c, L[0], L[1], L[2], L[3], f.x, f.y);
        }
    }
    act_split(acc, ah, al, act);

    // ---- Layer 4 chunks: MMA + direct v4 scatter, warp-independent ----
    process_chunk<0>(ah, al, lane, t, valid0, valid1, nrow0, orow0, nrow1, orow1,
                     e00, e01, e02, e10, e11, e12);
    process_chunk<1>(ah, al, lane, t, valid0, valid1, nrow0, orow0, nrow1, orow1,
                     e00, e01, e02, e10, e11, e12);
    process_chunk<2>(ah, al, lane, t, valid0, valid1, nrow0, orow0, nrow1, orow1,
                     e00, e01, e02, e10, e11, e12);
    process_chunk<3>(ah, al, lane, t, valid0, valid1, nrow0, orow0, nrow1, orow1,
                     e00, e01, e02, e10, e11, e12);
}

// ---------------------------------------------------------------------------
// Host
// ---------------------------------------------------------------------------
static float compute_act_cst() {
    const int    N = 20000;
    const double a = -14.0, b = 14.0;
    const double h = (b - a) / N;
    double sum = 0.0;
    for (int i = 0; i <= N; i++) {
        double xx  = a + h * i;
        double sig = 1.0 / (1.0 + exp(-xx));
        double sl  = xx * sig;
        double f   = exp(-0.5 * xx * xx) * sl * sl;
        double wq  = (i == 0 || i == N) ? 1.0 : ((i & 1) ? 4.0 : 2.0);
        sum += wq * f;
    }
    sum *= h / 3.0;
    sum /= sqrt(2.0 * M_PI);
    return (float)(1.0 / sqrt(sum));
}

extern "C" void kernel_launch(void* const* d_in, const int* in_sizes, int n_in,
                              void* d_out, int out_size)
{
    const float* node_feats = (const float*)d_in[0];
    const float* edge_attrs = (const float*)d_in[1];
    const int*   senders    = (const int*)d_in[2];
    const int*   receivers  = (const int*)d_in[3];
    const float* w0         = (const float*)d_in[4];
    const float* w1         = (const float*)d_in[5];
    const float* w2         = (const float*)d_in[6];
    const float* w3         = (const float*)d_in[7];
    float*       out        = (float*)d_out;

    int n_edges = in_sizes[2];
    if (n_edges > MAX_EDGES) n_edges = MAX_EDGES;

    float act = compute_act_cst();

    cudaMemsetAsync(d_out, 0, (size_t)out_size * sizeof(float));

    build_frags<<<(FRAG_TOTAL + 255) / 256, 256>>>(w0, w1, w2, w3);

    int blocks = (n_edges + 127) / 128;
    fused_kernel<<<blocks, 256>>>(edge_attrs, node_feats, senders,
                                  receivers, out, n_edges, act);
}

// round 7
// speedup vs baseline: 1.1046x; 1.0932x over previous
#include <cuda_runtime.h>
#include <cuda_bf16.h>
#include <math.h>
#include <stdint.h>

#define MAX_EDGES 320000

// Weight fragments, B-operand layout for mma.m16n8k16 (col-major B), hi/lo split.
// Entry = uint4 {b0_hi, b1_hi, b0_lo, b1_lo} per lane.
#define FRAG_L1 0
#define FRAG_L2 256
#define FRAG_L3 1280
#define FRAG_L4 2304
#define FRAG_TOTAL 6400
__device__ uint4 g_wfrag[FRAG_TOTAL];

// ---------------------------------------------------------------------------
// mma.sync m16n8k16 row.col bf16 -> f32  (compute_103-legal, runs on HMMA)
// ---------------------------------------------------------------------------
__device__ __forceinline__ void mma16816(float* c,
                                         uint32_t a0, uint32_t a1, uint32_t a2, uint32_t a3,
                                         uint32_t b0, uint32_t b1) {
    asm volatile(
        "mma.sync.aligned.m16n8k16.row.col.f32.bf16.bf16.f32 "
        "{%0,%1,%2,%3}, {%4,%5,%6,%7}, {%8,%9}, {%0,%1,%2,%3};"
        : "+f"(c[0]), "+f"(c[1]), "+f"(c[2]), "+f"(c[3])
        : "r"(a0), "r"(a1), "r"(a2), "r"(a3), "r"(b0), "r"(b1));
}

__device__ __forceinline__ void red4(float* p, float a, float b, float c, float d) {
    asm volatile("red.global.add.v4.f32 [%0], {%1,%2,%3,%4};"
                 :: "l"(p), "f"(a), "f"(b), "f"(c), "f"(d) : "memory");
}

__device__ __forceinline__ uint32_t pack2(float v0, float v1) {
    uint16_t u0 = __bfloat16_as_ushort(__float2bfloat16_rn(v0));
    uint16_t u1 = __bfloat16_as_ushort(__float2bfloat16_rn(v1));
    return (uint32_t)u0 | ((uint32_t)u1 << 16);
}

__device__ __forceinline__ void split2(float v0, float v1, uint32_t& hi, uint32_t& lo) {
    __nv_bfloat16 h0 = __float2bfloat16_rn(v0);
    __nv_bfloat16 h1 = __float2bfloat16_rn(v1);
    float r0 = v0 - __bfloat162float(h0);
    float r1 = v1 - __bfloat162float(h1);
    hi = (uint32_t)__bfloat16_as_ushort(h0) | ((uint32_t)__bfloat16_as_ushort(h1) << 16);
    lo = pack2(r0, r1);
}

__device__ __forceinline__ float silu_act(float x, float act) {
    return __fdividef(x, 1.0f + __expf(-x)) * act;
}

// ---------------------------------------------------------------------------
// Setup: fp32 weights -> fragment-ordered hi/lo bf16 (scales folded).
// L4 columns PERMUTED so D-fragment lane t owns 16 consecutive output
// channels: phys = chunk*64 + t*16 + nt_in*2 + j.
// ---------------------------------------------------------------------------
__global__ void build_frags(const float* __restrict__ w0, const float* __restrict__ w1,
                            const float* __restrict__ w2, const float* __restrict__ w3)
{
    int idx = blockIdx.x * blockDim.x + threadIdx.x;
    if (idx >= FRAG_TOTAL) return;

    const float* src; int K, N, ktiles, base; float scale;
    if (idx < FRAG_L2)      { base = FRAG_L1; src = w0; K = 8;  N = 64;  ktiles = 1; scale = 0.35355339059327373f; }
    else if (idx < FRAG_L3) { base = FRAG_L2; src = w1; K = 64; N = 64;  ktiles = 4; scale = 0.125f; }
    else if (idx < FRAG_L4) { base = FRAG_L3; src = w2; K = 64; N = 64;  ktiles = 4; scale = 0.125f; }
    else                    { base = FRAG_L4; src = w3; K = 64; N = 256; ktiles = 4; scale = 0.125f; }

    int fid  = idx - base;
    int lane = fid & 31, pair = fid >> 5;
    int kt = pair % ktiles, nt = pair / ktiles;
    int g = lane >> 2, t = lane & 3;

    int n;
    if (base == FRAG_L4) {
        int chunk = nt >> 3, nt_in = nt & 7;
        n = chunk * 64 + ((g >> 1) << 4) + nt_in * 2 + (g & 1);  // permuted
    } else {
        n = nt * 8 + g;
    }

    int kb = kt * 16 + 2 * t;
    int ks[4] = { kb, kb + 1, kb + 8, kb + 9 };

    uint16_t hi[4], lo[4];
#pragma unroll
    for (int i = 0; i < 4; i++) {
        float v = (ks[i] < K) ? src[ks[i] * N + n] * scale : 0.0f;
        __nv_bfloat16 h = __float2bfloat16_rn(v);
        float r = v - __bfloat162float(h);
        hi[i] = __bfloat16_as_ushort(h);
        lo[i] = __bfloat16_as_ushort(__float2bfloat16_rn(r));
    }
    uint4 o;
    o.x = (uint32_t)hi[0] | ((uint32_t)hi[1] << 16);
    o.y = (uint32_t)hi[2] | ((uint32_t)hi[3] << 16);
    o.z = (uint32_t)lo[0] | ((uint32_t)lo[1] << 16);
    o.w = (uint32_t)lo[2] | ((uint32_t)lo[3] << 16);
    g_wfrag[idx] = o;
}

// ---------------------------------------------------------------------------
// Fused kernel helpers
// ---------------------------------------------------------------------------
__device__ __forceinline__ void act_split(const float* acc, uint32_t* ah, uint32_t* al,
                                          float act) {
#pragma unroll
    for (int kt = 0; kt < 4; kt++) {
        const float* T0 = acc + (2 * kt) * 4;
        const float* T1 = acc + (2 * kt + 1) * 4;
        split2(silu_act(T0[0], act), silu_act(T0[1], act), ah[kt * 4 + 0], al[kt * 4 + 0]);
        split2(silu_act(T0[2], act), silu_act(T0[3], act), ah[kt * 4 + 1], al[kt * 4 + 1]);
        split2(silu_act(T1[0], act), silu_act(T1[1], act), ah[kt * 4 + 2], al[kt * 4 + 2]);
        split2(silu_act(T1[2], act), silu_act(T1[3], act), ah[kt * 4 + 3], al[kt * 4 + 3]);
    }
}

// Scatter one edge's 16 channels (lane-owned, consecutive) for chunk CHUNK.
// sel = 0 for row g, 2 for row g+8.
template <int CHUNK>
__device__ __forceinline__ void scatter_edge(const float* acc, int sel,
                                             const float* __restrict__ nrow,
                                             float* __restrict__ orow,
                                             float ev0, float ev1, float ev2, int t)
{
    const float S   = 0.25f;                    // 1/sqrt(16)
    const float IS3 = 0.57735026918962576f;     // 1/sqrt(3)
    int b16 = t * 16;
#pragma unroll
    for (int q = 0; q < 4; q++) {
        float m0 = acc[8 * q + sel]     * S;
        float m1 = acc[8 * q + sel + 1] * S;
        float m2 = acc[8 * q + 4 + sel]     * S;
        float m3 = acc[8 * q + 4 + sel + 1] * S;

        if (CHUNK == 0) {
            float4 ms = __ldg((const float4*)(nrow + b16 + 4 * q));
            red4(orow + b16 + 4 * q, ms.x * m0, ms.y * m1, ms.z * m2, ms.w * m3);
        } else if (CHUNK == 1) {
            const float4* vp = (const float4*)(nrow + 64 + 48 * t + 12 * q);
            float4 va = __ldg(vp), vb = __ldg(vp + 1), vc = __ldg(vp + 2);
            float t0 = (va.x * ev0 + va.y * ev1 + va.z * ev2) * IS3;
            float t1 = (va.w * ev0 + vb.x * ev1 + vb.y * ev2) * IS3;
            float t2 = (vb.z * ev0 + vb.w * ev1 + vc.x * ev2) * IS3;
            float t3 = (vc.y * ev0 + vc.z * ev1 + vc.w * ev2) * IS3;
            red4(orow + 64 + b16 + 4 * q, t0 * m0, t1 * m1, t2 * m2, t3 * m3);
        } else if (CHUNK == 2) {
            const float4* vp = (const float4*)(nrow + 64 + 48 * t + 12 * q);
            float4 va = __ldg(vp), vb = __ldg(vp + 1), vc = __ldg(vp + 2);
            float* po = orow + 128 + 48 * t + 12 * q;
            red4(po,     va.x * m0, va.y * m0, va.z * m0, va.w * m1);
            red4(po + 4, vb.x * m1, vb.y * m1, vb.z * m2, vb.w * m2);
            red4(po + 8, vc.x * m2, vc.y * m3, vc.z * m3, vc.w * m3);
        } else {
            float4 ms = __ldg((const float4*)(nrow + b16 + 4 * q));
            float d0 = ms.x * m0, d1 = ms.y * m1, d2 = ms.z * m2, d3 = ms.w * m3;
            float* po = orow + 320 + 48 * t + 12 * q;
            red4(po,     d0 * ev0, d0 * ev1, d0 * ev2, d1 * ev0);
            red4(po + 4, d1 * ev1, d1 * ev2, d2 * ev0, d2 * ev1);
            red4(po + 8, d2 * ev2, d3 * ev0, d3 * ev1, d3 * ev2);
        }
    }
}

// Layer-4 chunk: 12 MMAs then direct per-lane scatter; per-edge metadata
// fetched transiently from smem (keeps register lifetime short).
template <int CHUNK>
__device__ __forceinline__ void process_chunk(
    const uint32_t* ah, const uint32_t* al, int lane, int t, int warp, int g,
    bool valid0, bool valid1,
    const int* sh_s, const int* sh_r, const float* sh_ev,
    const float* __restrict__ node_feats, float* __restrict__ out)
{
    float acc[32];
#pragma unroll
    for (int i = 0; i < 32; i++) acc[i] = 0.f;
#pragma unroll
    for (int nt = 0; nt < 8; nt++) {
#pragma unroll
        for (int kt = 0; kt < 4; kt++) {
            uint4 f = __ldg(&g_wfrag[FRAG_L4 + ((CHUNK * 8 + nt) * 4 + kt) * 32 + lane]);
            float* c = &acc[nt * 4];
            const uint32_t* A = &ah[kt * 4];
            const uint32_t* L = &al[kt * 4];
            mma16816(c, A[0], A[1], A[2], A[3], f.x, f.y);
            mma16816(c, A[0], A[1], A[2], A[3], f.z, f.w);
            mma16816(c, L[0], L[1], L[2], L[3], f.x, f.y);
        }
    }
    if (valid0) {
        int el = warp * 16 + g;
        const float* nrow = node_feats + (size_t)sh_s[el] * 256;
        float*       orow = out + (size_t)sh_r[el] * 512;
        scatter_edge<CHUNK>(acc, 0, nrow, orow,
                            sh_ev[el * 3], sh_ev[el * 3 + 1], sh_ev[el * 3 + 2], t);
    }
    if (valid1) {
        int el = warp * 16 + g + 8;
        const float* nrow = node_feats + (size_t)sh_s[el] * 256;
        float*       orow = out + (size_t)sh_r[el] * 512;
        scatter_edge<CHUNK>(acc, 2, nrow, orow,
                            sh_ev[el * 3], sh_ev[el * 3 + 1], sh_ev[el * 3 + 2], t);
    }
}

// ---------------------------------------------------------------------------
// Fused kernel: MLP (chained warp MMAs) + direct scatter-add.
// Block = 128 threads = 4 warps = 64 edges (16 per warp). Metadata in smem.
// ---------------------------------------------------------------------------
__global__ void __launch_bounds__(128, 5)
fused_kernel(const float* __restrict__ edge_attrs,
             const float* __restrict__ node_feats,
             const int* __restrict__ senders,
             const int* __restrict__ receivers,
             float* __restrict__ out,
             int n_edges, float act)
{
    __shared__ int   sh_s[64];
    __shared__ int   sh_r[64];
    __shared__ float sh_ev[64 * 3];

    int tid = threadIdx.x, lane = tid & 31, warp = tid >> 5;
    int g = lane >> 2, t = lane & 3;
    int wbase = blockIdx.x * 64 + warp * 16;
    int e0 = wbase + g, e1 = e0 + 8;
    bool valid0 = e0 < n_edges, valid1 = e1 < n_edges;

    // Each warp loads its own 16 edges' metadata (warp-local, no block sync).
    if (lane < 16) {
        int e = wbase + lane;
        int el = warp * 16 + lane;
        if (e < n_edges) {
            sh_s[el] = __ldg(senders + e);
            sh_r[el] = __ldg(receivers + e);
            const float* ea = edge_attrs + (size_t)e * 11;
            sh_ev[el * 3 + 0] = __ldg(ea + 8);
            sh_ev[el * 3 + 1] = __ldg(ea + 9);
            sh_ev[el * 3 + 2] = __ldg(ea + 10);
        } else {
            sh_s[el] = 0; sh_r[el] = 0;
            sh_ev[el * 3 + 0] = 0.f; sh_ev[el * 3 + 1] = 0.f; sh_ev[el * 3 + 2] = 0.f;
        }
    }
    __syncwarp();

    // ---- Layer 1 A fragments from edge_attrs (K=8, cols 8..15 zero) ----
    float x00 = 0.f, x01 = 0.f, x10 = 0.f, x11 = 0.f;
    if (valid0) {
        const float* p = edge_attrs + (size_t)e0 * 11 + 2 * t;
        x00 = __ldg(p); x01 = __ldg(p + 1);
    }
    if (valid1) {
        const float* p = edge_attrs + (size_t)e1 * 11 + 2 * t;
        x10 = __ldg(p); x11 = __ldg(p + 1);
    }
    uint32_t a0h, a0l, a1h, a1l;
    split2(x00, x01, a0h, a0l);
    split2(x10, x11, a1h, a1l);

    float acc[32];
    uint32_t ah[16], al[16];

    // ---- Layer 1: N=64, single k-tile ----
#pragma unroll
    for (int i = 0; i < 32; i++) acc[i] = 0.f;
#pragma unroll
    for (int nt = 0; nt < 8; nt++) {
        uint4 f = __ldg(&g_wfrag[FRAG_L1 + nt * 32 + lane]);
        float* c = &acc[nt * 4];
        mma16816(c, a0h, a1h, 0u, 0u, f.x, f.y);
        mma16816(c, a0h, a1h, 0u, 0u, f.z, f.w);
        mma16816(c, a0l, a1l, 0u, 0u, f.x, f.y);
    }
    act_split(acc, ah, al, act);

    // ---- Layer 2: 64x64 ----
#pragma unroll
    for (int i = 0; i < 32; i++) acc[i] = 0.f;
#pragma unroll
    for (int nt = 0; nt < 8; nt++) {
#pragma unroll
        for (int kt = 0; kt < 4; kt++) {
            uint4 f = __ldg(&g_wfrag[FRAG_L2 + (nt * 4 + kt) * 32 + lane]);
            float* c = &acc[nt * 4];
            const uint32_t* A = &ah[kt * 4];
            const uint32_t* L = &al[kt * 4];
            mma16816(c, A[0], A[1], A[2], A[3], f.x, f.y);
            mma16816(c, A[0], A[1], A[2], A[3], f.z, f.w);
            mma16816(c, L[0], L[1], L[2], L[3], f.x, f.y);
        }
    }
    act_split(acc, ah, al, act);

    // ---- Layer 3: 64x64 ----
#pragma unroll
    for (int i = 0; i < 32; i++) acc[i] = 0.f;
#pragma unroll
    for (int nt = 0; nt < 8; nt++) {
#pragma unroll
        for (int kt = 0; kt < 4; kt++) {
            uint4 f = __ldg(&g_wfrag[FRAG_L3 + (nt * 4 + kt) * 32 + lane]);
            float* c = &acc[nt * 4];
            const uint32_t* A = &ah[kt * 4];
            const uint32_t* L = &al[kt * 4];
            mma16816(c, A[0], A[1], A[2], A[3], f.x, f.y);
            mma16816(c, A[0], A[1], A[2], A[3], f.z, f.w);
            mma16816(c, L[0], L[1], L[2], L[3], f.x, f.y);
        }
    }
    act_split(acc, ah, al, act);

    // ---- Layer 4 chunks: MMA + direct v4 scatter, warp-independent ----
    process_chunk<0>(ah, al, lane, t, warp, g, valid0, valid1,
                     sh_s, sh_r, sh_ev, node_feats, out);
    process_chunk<1>(ah, al, lane, t, warp, g, valid0, valid1,
                     sh_s, sh_r, sh_ev, node_feats, out);
    process_chunk<2>(ah, al, lane, t, warp, g, valid0, valid1,
                     sh_s, sh_r, sh_ev, node_feats, out);
    process_chunk<3>(ah, al, lane, t, warp, g, valid0, valid1,
                     sh_s, sh_r, sh_ev, node_feats, out);
}

// ---------------------------------------------------------------------------
// Host
// ---------------------------------------------------------------------------
static float compute_act_cst() {
    const int    N = 20000;
    const double a = -14.0, b = 14.0;
    const double h = (b - a) / N;
    double sum = 0.0;
    for (int i = 0; i <= N; i++) {
        double xx  = a + h * i;
        double sig = 1.0 / (1.0 + exp(-xx));
        double sl  = xx * sig;
        double f   = exp(-0.5 * xx * xx) * sl * sl;
        double wq  = (i == 0 || i == N) ? 1.0 : ((i & 1) ? 4.0 : 2.0);
        sum += wq * f;
    }
    sum *= h / 3.0;
    sum /= sqrt(2.0 * M_PI);
    return (float)(1.0 / sqrt(sum));
}

extern "C" void kernel_launch(void* const* d_in, const int* in_sizes, int n_in,
                              void* d_out, int out_size)
{
    const float* node_feats = (const float*)d_in[0];
    const float* edge_attrs = (const float*)d_in[1];
    const int*   senders    = (const int*)d_in[2];
    const int*   receivers  = (const int*)d_in[3];
    const float* w0         = (const float*)d_in[4];
    const float* w1         = (const float*)d_in[5];
    const float* w2         = (const float*)d_in[6];
    const float* w3         = (const float*)d_in[7];
    float*       out        = (float*)d_out;

    int n_edges = in_sizes[2];
    if (n_edges > MAX_EDGES) n_edges = MAX_EDGES;

    float act = compute_act_cst();

    cudaMemsetAsync(d_out, 0, (size_t)out_size * sizeof(float));

    build_frags<<<(FRAG_TOTAL + 255) / 256, 256>>>(w0, w1, w2, w3);

    int blocks = (n_edges + 63) / 64;
    fused_kernel<<<blocks, 128>>>(edge_attrs, node_feats, senders,
                                  receivers, out, n_edges, act);
}

// round 8
// speedup vs baseline: 1.2565x; 1.1375x over previous
#include <cuda_runtime.h>
#include <cuda_fp16.h>
#include <math.h>
#include <stdint.h>

#define MAX_EDGES 320000

// Weight fragments, B-operand layout for mma.m16n8k16 (col-major B), fp16.
// Entry = uint2 {b0, b1} per lane (k16 B-fragment).
#define FRAG_L1 0
#define FRAG_L2 256
#define FRAG_L3 1280
#define FRAG_L4 2304
#define FRAG_TOTAL 6400
__device__ uint2 g_wfrag[FRAG_TOTAL];

// ---------------------------------------------------------------------------
// mma.sync m16n8k16 row.col fp16 -> f32  (compute_103-legal, runs on HMMA)
// ---------------------------------------------------------------------------
__device__ __forceinline__ void mma16816(float* c,
                                         uint32_t a0, uint32_t a1, uint32_t a2, uint32_t a3,
                                         uint32_t b0, uint32_t b1) {
    asm volatile(
        "mma.sync.aligned.m16n8k16.row.col.f32.f16.f16.f32 "
        "{%0,%1,%2,%3}, {%4,%5,%6,%7}, {%8,%9}, {%0,%1,%2,%3};"
        : "+f"(c[0]), "+f"(c[1]), "+f"(c[2]), "+f"(c[3])
        : "r"(a0), "r"(a1), "r"(a2), "r"(a3), "r"(b0), "r"(b1));
}

__device__ __forceinline__ void red4(float* p, float a, float b, float c, float d) {
    asm volatile("red.global.add.v4.f32 [%0], {%1,%2,%3,%4};"
                 :: "l"(p), "f"(a), "f"(b), "f"(c), "f"(d) : "memory");
}

// Split (v0,v1) into fp16 hi pair + fp16 residual-lo pair.
__device__ __forceinline__ void split2(float v0, float v1, uint32_t& hi, uint32_t& lo) {
    __half h0 = __float2half_rn(v0);
    __half h1 = __float2half_rn(v1);
    float r0 = v0 - __half2float(h0);
    float r1 = v1 - __half2float(h1);
    __half l0 = __float2half_rn(r0);
    __half l1 = __float2half_rn(r1);
    hi = (uint32_t)__half_as_ushort(h0) | ((uint32_t)__half_as_ushort(h1) << 16);
    lo = (uint32_t)__half_as_ushort(l0) | ((uint32_t)__half_as_ushort(l1) << 16);
}

__device__ __forceinline__ float silu_act(float x, float act) {
    return __fdividef(x, 1.0f + __expf(-x)) * act;
}

// ---------------------------------------------------------------------------
// Setup: fp32 weights -> fragment-ordered fp16 (scales folded).
// L4 columns PERMUTED so D-fragment lane t owns 16 consecutive output
// channels: phys = chunk*64 + t*16 + nt_in*2 + j.
// ---------------------------------------------------------------------------
__global__ void build_frags(const float* __restrict__ w0, const float* __restrict__ w1,
                            const float* __restrict__ w2, const float* __restrict__ w3)
{
    int idx = blockIdx.x * blockDim.x + threadIdx.x;
    if (idx >= FRAG_TOTAL) return;

    const float* src; int K, N, ktiles, base; float scale;
    if (idx < FRAG_L2)      { base = FRAG_L1; src = w0; K = 8;  N = 64;  ktiles = 1; scale = 0.35355339059327373f; }
    else if (idx < FRAG_L3) { base = FRAG_L2; src = w1; K = 64; N = 64;  ktiles = 4; scale = 0.125f; }
    else if (idx < FRAG_L4) { base = FRAG_L3; src = w2; K = 64; N = 64;  ktiles = 4; scale = 0.125f; }
    else                    { base = FRAG_L4; src = w3; K = 64; N = 256; ktiles = 4; scale = 0.125f; }

    int fid  = idx - base;
    int lane = fid & 31, pair = fid >> 5;
    int kt = pair % ktiles, nt = pair / ktiles;
    int g = lane >> 2, t = lane & 3;

    int n;
    if (base == FRAG_L4) {
        int chunk = nt >> 3, nt_in = nt & 7;
        n = chunk * 64 + ((g >> 1) << 4) + nt_in * 2 + (g & 1);  // permuted
    } else {
        n = nt * 8 + g;
    }

    int kb = kt * 16 + 2 * t;
    int ks[4] = { kb, kb + 1, kb + 8, kb + 9 };

    uint16_t h[4];
#pragma unroll
    for (int i = 0; i < 4; i++) {
        float v = (ks[i] < K) ? src[ks[i] * N + n] * scale : 0.0f;
        h[i] = __half_as_ushort(__float2half_rn(v));
    }
    uint2 o;
    o.x = (uint32_t)h[0] | ((uint32_t)h[1] << 16);
    o.y = (uint32_t)h[2] | ((uint32_t)h[3] << 16);
    g_wfrag[idx] = o;
}

// ---------------------------------------------------------------------------
// Fused kernel helpers
// ---------------------------------------------------------------------------
__device__ __forceinline__ void act_split(const float* acc, uint32_t* ah, uint32_t* al,
                                          float act) {
#pragma unroll
    for (int kt = 0; kt < 4; kt++) {
        const float* T0 = acc + (2 * kt) * 4;
        const float* T1 = acc + (2 * kt + 1) * 4;
        split2(silu_act(T0[0], act), silu_act(T0[1], act), ah[kt * 4 + 0], al[kt * 4 + 0]);
        split2(silu_act(T0[2], act), silu_act(T0[3], act), ah[kt * 4 + 1], al[kt * 4 + 1]);
        split2(silu_act(T1[0], act), silu_act(T1[1], act), ah[kt * 4 + 2], al[kt * 4 + 2]);
        split2(silu_act(T1[2], act), silu_act(T1[3], act), ah[kt * 4 + 3], al[kt * 4 + 3]);
    }
}

// Scatter one edge's 16 channels (lane-owned, consecutive) for chunk CHUNK.
// sel = 0 for row g, 2 for row g+8.
template <int CHUNK>
__device__ __forceinline__ void scatter_edge(const float* acc, int sel,
                                             const float* __restrict__ nrow,
                                             float* __restrict__ orow,
                                             float ev0, float ev1, float ev2, int t)
{
    const float S   = 0.25f;                    // 1/sqrt(16)
    const float IS3 = 0.57735026918962576f;     // 1/sqrt(3)
    int b16 = t * 16;
#pragma unroll
    for (int q = 0; q < 4; q++) {
        float m0 = acc[8 * q + sel]     * S;
        float m1 = acc[8 * q + sel + 1] * S;
        float m2 = acc[8 * q + 4 + sel]     * S;
        float m3 = acc[8 * q + 4 + sel + 1] * S;

        if (CHUNK == 0) {
            float4 ms = __ldg((const float4*)(nrow + b16 + 4 * q));
            red4(orow + b16 + 4 * q, ms.x * m0, ms.y * m1, ms.z * m2, ms.w * m3);
        } else if (CHUNK == 1) {
            const float4* vp = (const float4*)(nrow + 64 + 48 * t + 12 * q);
            float4 va = __ldg(vp), vb = __ldg(vp + 1), vc = __ldg(vp + 2);
            float t0 = (va.x * ev0 + va.y * ev1 + va.z * ev2) * IS3;
            float t1 = (va.w * ev0 + vb.x * ev1 + vb.y * ev2) * IS3;
            float t2 = (vb.z * ev0 + vb.w * ev1 + vc.x * ev2) * IS3;
            float t3 = (vc.y * ev0 + vc.z * ev1 + vc.w * ev2) * IS3;
            red4(orow + 64 + b16 + 4 * q, t0 * m0, t1 * m1, t2 * m2, t3 * m3);
        } else if (CHUNK == 2) {
            const float4* vp = (const float4*)(nrow + 64 + 48 * t + 12 * q);
            float4 va = __ldg(vp), vb = __ldg(vp + 1), vc = __ldg(vp + 2);
            float* po = orow + 128 + 48 * t + 12 * q;
            red4(po,     va.x * m0, va.y * m0, va.z * m0, va.w * m1);
            red4(po + 4, vb.x * m1, vb.y * m1, vb.z * m2, vb.w * m2);
            red4(po + 8, vc.x * m2, vc.y * m3, vc.z * m3, vc.w * m3);
        } else {
            float4 ms = __ldg((const float4*)(nrow + b16 + 4 * q));
            float d0 = ms.x * m0, d1 = ms.y * m1, d2 = ms.z * m2, d3 = ms.w * m3;
            float* po = orow + 320 + 48 * t + 12 * q;
            red4(po,     d0 * ev0, d0 * ev1, d0 * ev2, d1 * ev0);
            red4(po + 4, d1 * ev1, d1 * ev2, d2 * ev0, d2 * ev1);
            red4(po + 8, d2 * ev2, d3 * ev0, d3 * ev1, d3 * ev2);
        }
    }
}

// Layer-4 chunk: 8 MMAs then direct per-lane scatter; per-edge metadata
// fetched transiently from smem (keeps register lifetime short).
template <int CHUNK>
__device__ __forceinline__ void process_chunk(
    const uint32_t* ah, const uint32_t* al, int lane, int t, int warp, int g,
    bool valid0, bool valid1,
    const int* sh_s, const int* sh_r, const float* sh_ev,
    const float* __restrict__ node_feats, float* __restrict__ out)
{
    float acc[32];
#pragma unroll
    for (int i = 0; i < 32; i++) acc[i] = 0.f;
#pragma unroll
    for (int nt = 0; nt < 8; nt++) {
#pragma unroll
        for (int kt = 0; kt < 4; kt++) {
            uint2 f = __ldg(&g_wfrag[FRAG_L4 + ((CHUNK * 8 + nt) * 4 + kt) * 32 + lane]);
            float* c = &acc[nt * 4];
            const uint32_t* A = &ah[kt * 4];
            const uint32_t* L = &al[kt * 4];
            mma16816(c, A[0], A[1], A[2], A[3], f.x, f.y);
            mma16816(c, L[0], L[1], L[2], L[3], f.x, f.y);
        }
    }
    if (valid0) {
        int el = warp * 16 + g;
        const float* nrow = node_feats + (size_t)sh_s[el] * 256;
        float*       orow = out + (size_t)sh_r[el] * 512;
        scatter_edge<CHUNK>(acc, 0, nrow, orow,
                            sh_ev[el * 3], sh_ev[el * 3 + 1], sh_ev[el * 3 + 2], t);
    }
    if (valid1) {
        int el = warp * 16 + g + 8;
        const float* nrow = node_feats + (size_t)sh_s[el] * 256;
        float*       orow = out + (size_t)sh_r[el] * 512;
        scatter_edge<CHUNK>(acc, 2, nrow, orow,
                            sh_ev[el * 3], sh_ev[el * 3 + 1], sh_ev[el * 3 + 2], t);
    }
}

// ---------------------------------------------------------------------------
// Fused kernel: MLP (chained warp MMAs, fp16 2-term) + direct scatter-add.
// Block = 128 threads = 4 warps = 64 edges (16 per warp). Metadata in smem.
// ---------------------------------------------------------------------------
__global__ void __launch_bounds__(128, 5)
fused_kernel(const float* __restrict__ edge_attrs,
             const float* __restrict__ node_feats,
             const int* __restrict__ senders,
             const int* __restrict__ receivers,
             float* __restrict__ out,
             int n_edges, float act)
{
    __shared__ int   sh_s[64];
    __shared__ int   sh_r[64];
    __shared__ float sh_ev[64 * 3];

    int tid = threadIdx.x, lane = tid & 31, warp = tid >> 5;
    int g = lane >> 2, t = lane & 3;
    int wbase = blockIdx.x * 64 + warp * 16;
    int e0 = wbase + g, e1 = e0 + 8;
    bool valid0 = e0 < n_edges, valid1 = e1 < n_edges;

    // Each warp loads its own 16 edges' metadata (warp-local, no block sync).
    if (lane < 16) {
        int e = wbase + lane;
        int el = warp * 16 + lane;
        if (e < n_edges) {
            sh_s[el] = __ldg(senders + e);
            sh_r[el] = __ldg(receivers + e);
            const float* ea = edge_attrs + (size_t)e * 11;
            sh_ev[el * 3 + 0] = __ldg(ea + 8);
            sh_ev[el * 3 + 1] = __ldg(ea + 9);
            sh_ev[el * 3 + 2] = __ldg(ea + 10);
        } else {
            sh_s[el] = 0; sh_r[el] = 0;
            sh_ev[el * 3 + 0] = 0.f; sh_ev[el * 3 + 1] = 0.f; sh_ev[el * 3 + 2] = 0.f;
        }
    }
    __syncwarp();

    // ---- Layer 1 A fragments from edge_attrs (K=8, cols 8..15 zero) ----
    float x00 = 0.f, x01 = 0.f, x10 = 0.f, x11 = 0.f;
    if (valid0) {
        const float* p = edge_attrs + (size_t)e0 * 11 + 2 * t;
        x00 = __ldg(p); x01 = __ldg(p + 1);
    }
    if (valid1) {
        const float* p = edge_attrs + (size_t)e1 * 11 + 2 * t;
        x10 = __ldg(p); x11 = __ldg(p + 1);
    }
    uint32_t a0h, a0l, a1h, a1l;
    split2(x00, x01, a0h, a0l);
    split2(x10, x11, a1h, a1l);

    float acc[32];
    uint32_t ah[16], al[16];

    // ---- Layer 1: N=64, single k-tile ----
#pragma unroll
    for (int i = 0; i < 32; i++) acc[i] = 0.f;
#pragma unroll
    for (int nt = 0; nt < 8; nt++) {
        uint2 f = __ldg(&g_wfrag[FRAG_L1 + nt * 32 + lane]);
        float* c = &acc[nt * 4];
        mma16816(c, a0h, a1h, 0u, 0u, f.x, f.y);
        mma16816(c, a0l, a1l, 0u, 0u, f.x, f.y);
    }
    act_split(acc, ah, al, act);

    // ---- Layer 2: 64x64 ----
#pragma unroll
    for (int i = 0; i < 32; i++) acc[i] = 0.f;
#pragma unroll
    for (int nt = 0; nt < 8; nt++) {
#pragma unroll
        for (int kt = 0; kt < 4; kt++) {
            uint2 f = __ldg(&g_wfrag[FRAG_L2 + (nt * 4 + kt) * 32 + lane]);
            float* c = &acc[nt * 4];
            const uint32_t* A = &ah[kt * 4];
            const uint32_t* L = &al[kt * 4];
            mma16816(c, A[0], A[1], A[2], A[3], f.x, f.y);
            mma16816(c, L[0], L[1], L[2], L[3], f.x, f.y);
        }
    }
    act_split(acc, ah, al, act);

    // ---- Layer 3: 64x64 ----
#pragma unroll
    for (int i = 0; i < 32; i++) acc[i] = 0.f;
#pragma unroll
    for (int nt = 0; nt < 8; nt++) {
#pragma unroll
        for (int kt = 0; kt < 4; kt++) {
            uint2 f = __ldg(&g_wfrag[FRAG_L3 + (nt * 4 + kt) * 32 + lane]);
            float* c = &acc[nt * 4];
            const uint32_t* A = &ah[kt * 4];
            const uint32_t* L = &al[kt * 4];
            mma16816(c, A[0], A[1], A[2], A[3], f.x, f.y);
            mma16816(c, L[0], L[1], L[2], L[3], f.x, f.y);
        }
    }
    act_split(acc, ah, al, act);

    // ---- Layer 4 chunks: MMA + direct v4 scatter, warp-independent ----
    process_chunk<0>(ah, al, lane, t, warp, g, valid0, valid1,
                     sh_s, sh_r, sh_ev, node_feats, out);
    process_chunk<1>(ah, al, lane, t, warp, g, valid0, valid1,
                     sh_s, sh_r, sh_ev, node_feats, out);
    process_chunk<2>(ah, al, lane, t, warp, g, valid0, valid1,
                     sh_s, sh_r, sh_ev, node_feats, out);
    process_chunk<3>(ah, al, lane, t, warp, g, valid0, valid1,
                     sh_s, sh_r, sh_ev, node_feats, out);
}

// ---------------------------------------------------------------------------
// Host
// ---------------------------------------------------------------------------
static float compute_act_cst() {
    const int    N = 20000;
    const double a = -14.0, b = 14.0;
    const double h = (b - a) / N;
    double sum = 0.0;
    for (int i = 0; i <= N; i++) {
        double xx  = a + h * i;
        double sig = 1.0 / (1.0 + exp(-xx));
        double sl  = xx * sig;
        double f   = exp(-0.5 * xx * xx) * sl * sl;
        double wq  = (i == 0 || i == N) ? 1.0 : ((i & 1) ? 4.0 : 2.0);
        sum += wq * f;
    }
    sum *= h / 3.0;
    sum /= sqrt(2.0 * M_PI);
    return (float)(1.0 / sqrt(sum));
}

extern "C" void kernel_launch(void* const* d_in, const int* in_sizes, int n_in,
                              void* d_out, int out_size)
{
    const float* node_feats = (const float*)d_in[0];
    const float* edge_attrs = (const float*)d_in[1];
    const int*   senders    = (const int*)d_in[2];
    const int*   receivers  = (const int*)d_in[3];
    const float* w0         = (const float*)d_in[4];
    const float* w1         = (const float*)d_in[5];
    const float* w2         = (const float*)d_in[6];
    const float* w3         = (const float*)d_in[7];
    float*       out        = (float*)d_out;

    int n_edges = in_sizes[2];
    if (n_edges > MAX_EDGES) n_edges = MAX_EDGES;

    float act = compute_act_cst();

    cudaMemsetAsync(d_out, 0, (size_t)out_size * sizeof(float));

    build_frags<<<(FRAG_TOTAL + 255) / 256, 256>>>(w0, w1, w2, w3);

    int blocks = (n_edges + 63) / 64;
    fused_kernel<<<blocks, 128>>>(edge_attrs, node_feats, senders,
                                  receivers, out, n_edges, act);
}

// round 10
// speedup vs baseline: 1.6591x; 1.3204x over previous
#include <cuda_runtime.h>
#include <cuda_fp16.h>
#include <math.h>
#include <stdint.h>

#define MAX_EDGES 320000

// Weight fragments, B-operand layout for mma.m16n8k16 (col-major B), fp16.
// Entry = uint2 {b0, b1} per lane (k16 B-fragment).
#define FRAG_L1 0
#define FRAG_L2 256
#define FRAG_L3 1280
#define FRAG_L4 2304
#define FRAG_TOTAL 6400
__device__ uint2 g_wfrag[FRAG_TOTAL];

#define MSTRIDE 68   /* floats per staged mix row (64 + 4 pad) */

// ---------------------------------------------------------------------------
// mma.sync m16n8k16 row.col fp16 -> f32  (compute_103-legal, runs on HMMA)
// ---------------------------------------------------------------------------
__device__ __forceinline__ void mma16816(float* c,
                                         uint32_t a0, uint32_t a1, uint32_t a2, uint32_t a3,
                                         uint32_t b0, uint32_t b1) {
    asm volatile(
        "mma.sync.aligned.m16n8k16.row.col.f32.f16.f16.f32 "
        "{%0,%1,%2,%3}, {%4,%5,%6,%7}, {%8,%9}, {%0,%1,%2,%3};"
        : "+f"(c[0]), "+f"(c[1]), "+f"(c[2]), "+f"(c[3])
        : "r"(a0), "r"(a1), "r"(a2), "r"(a3), "r"(b0), "r"(b1));
}

__device__ __forceinline__ void red4(float* p, float a, float b, float c, float d) {
    asm volatile("red.global.add.v4.f32 [%0], {%1,%2,%3,%4};"
                 :: "l"(p), "f"(a), "f"(b), "f"(c), "f"(d) : "memory");
}

// Split (v0,v1) into fp16 hi pair + fp16 residual-lo pair.
__device__ __forceinline__ void split2(float v0, float v1, uint32_t& hi, uint32_t& lo) {
    __half h0 = __float2half_rn(v0);
    __half h1 = __float2half_rn(v1);
    float r0 = v0 - __half2float(h0);
    float r1 = v1 - __half2float(h1);
    __half l0 = __float2half_rn(r0);
    __half l1 = __float2half_rn(r1);
    hi = (uint32_t)__half_as_ushort(h0) | ((uint32_t)__half_as_ushort(h1) << 16);
    lo = (uint32_t)__half_as_ushort(l0) | ((uint32_t)__half_as_ushort(l1) << 16);
}

__device__ __forceinline__ float silu_act(float x, float act) {
    return __fdividef(x, 1.0f + __expf(-x)) * act;
}

// ---------------------------------------------------------------------------
// Setup: fp32 weights -> fragment-ordered fp16 (scales folded).
// L4: columns PERMUTED (lane t owns 16 consecutive channels) AND the message
// normalization 1/sqrt(16) is folded into the weight scale.
// ---------------------------------------------------------------------------
__global__ void build_frags(const float* __restrict__ w0, const float* __restrict__ w1,
                            const float* __restrict__ w2, const float* __restrict__ w3)
{
    int idx = blockIdx.x * blockDim.x + threadIdx.x;
    if (idx >= FRAG_TOTAL) return;

    const float* src; int K, N, ktiles, base; float scale;
    if (idx < FRAG_L2)      { base = FRAG_L1; src = w0; K = 8;  N = 64;  ktiles = 1; scale = 0.35355339059327373f; }
    else if (idx < FRAG_L3) { base = FRAG_L2; src = w1; K = 64; N = 64;  ktiles = 4; scale = 0.125f; }
    else if (idx < FRAG_L4) { base = FRAG_L3; src = w2; K = 64; N = 64;  ktiles = 4; scale = 0.125f; }
    else                    { base = FRAG_L4; src = w3; K = 64; N = 256; ktiles = 4; scale = 0.125f * 0.25f; }

    int fid  = idx - base;
    int lane = fid & 31, pair = fid >> 5;
    int kt = pair % ktiles, nt = pair / ktiles;
    int g = lane >> 2, t = lane & 3;

    int n;
    if (base == FRAG_L4) {
        int chunk = nt >> 3, nt_in = nt & 7;
        n = chunk * 64 + ((g >> 1) << 4) + nt_in * 2 + (g & 1);  // permuted
    } else {
        n = nt * 8 + g;
    }

    int kb = kt * 16 + 2 * t;
    int ks[4] = { kb, kb + 1, kb + 8, kb + 9 };

    uint16_t h[4];
#pragma unroll
    for (int i = 0; i < 4; i++) {
        float v = (ks[i] < K) ? src[ks[i] * N + n] * scale : 0.0f;
        h[i] = __half_as_ushort(__float2half_rn(v));
    }
    uint2 o;
    o.x = (uint32_t)h[0] | ((uint32_t)h[1] << 16);
    o.y = (uint32_t)h[2] | ((uint32_t)h[3] << 16);
    g_wfrag[idx] = o;
}

// ---------------------------------------------------------------------------
// Fused kernel helpers
// ---------------------------------------------------------------------------
__device__ __forceinline__ void act_split(const float* acc, uint32_t* ah, uint32_t* al,
                                          float act) {
#pragma unroll
    for (int kt = 0; kt < 4; kt++) {
        const float* T0 = acc + (2 * kt) * 4;
        const float* T1 = acc + (2 * kt + 1) * 4;
        split2(silu_act(T0[0], act), silu_act(T0[1], act), ah[kt * 4 + 0], al[kt * 4 + 0]);
        split2(silu_act(T0[2], act), silu_act(T0[3], act), ah[kt * 4 + 1], al[kt * 4 + 1]);
        split2(silu_act(T1[0], act), silu_act(T1[1], act), ah[kt * 4 + 2], al[kt * 4 + 2]);
        split2(silu_act(T1[2], act), silu_act(T1[3], act), ah[kt * 4 + 3], al[kt * 4 + 3]);
    }
}

// Layer-4 chunk: 8 MMAs -> stage 16x64 mix tile in warp-private smem ->
// half-warp-per-edge coalesced gather + red.v4 scatter. Only __syncwarp.
template <int CHUNK>
__device__ __forceinline__ void process_chunk(
    const uint32_t* ah, const uint32_t* al, int lane, int t, int g,
    float* wmsg,                    // warp-private [16][MSTRIDE]
    const int* sh_s, const int* sh_r, const float* sh_ev,   // warp-offset views
    int edges_left,                 // n_edges - (block*64 + warp*16)
    const float* __restrict__ node_feats, float* __restrict__ out)
{
    float acc[32];
#pragma unroll
    for (int i = 0; i < 32; i++) acc[i] = 0.f;
#pragma unroll
    for (int nt = 0; nt < 8; nt++) {
#pragma unroll
        for (int kt = 0; kt < 4; kt++) {
            uint2 f = __ldg(&g_wfrag[FRAG_L4 + ((CHUNK * 8 + nt) * 4 + kt) * 32 + lane]);
            float* c = &acc[nt * 4];
            const uint32_t* A = &ah[kt * 4];
            const uint32_t* L = &al[kt * 4];
            mma16816(c, A[0], A[1], A[2], A[3], f.x, f.y);
            mma16816(c, L[0], L[1], L[2], L[3], f.x, f.y);
        }
    }

    // Stage: lane owns channels t*16+4q..+3 for rows g and g+8.
    __syncwarp();
#pragma unroll
    for (int q = 0; q < 4; q++) {
        *(float4*)&wmsg[g * MSTRIDE + t * 16 + 4 * q] =
            make_float4(acc[8 * q + 0], acc[8 * q + 1], acc[8 * q + 4], acc[8 * q + 5]);
        *(float4*)&wmsg[(g + 8) * MSTRIDE + t * 16 + 4 * q] =
            make_float4(acc[8 * q + 2], acc[8 * q + 3], acc[8 * q + 6], acc[8 * q + 7]);
    }
    __syncwarp();

    const float IS3 = 0.57735026918962576f;     // 1/sqrt(3)
    int half = lane >> 4;
    int l = lane & 15;

#pragma unroll 1
    for (int p = 0; p < 8; p++) {
        int el = 2 * p + half;                  // edge row within warp tile
        bool evalid = el < edges_left;
        int s = sh_s[el], r = sh_r[el];
        float ev0 = sh_ev[el * 3], ev1 = sh_ev[el * 3 + 1], ev2 = sh_ev[el * 3 + 2];
        const float* nrow = node_feats + (size_t)s * 256;
        float* orow = out + (size_t)r * 512;
        float4 mx = *(const float4*)&wmsg[el * MSTRIDE + 4 * l];

        if (CHUNK == 0) {
            float4 ms = __ldg((const float4*)(nrow + 4 * l));
            if (evalid)
                red4(orow + 4 * l, ms.x * mx.x, ms.y * mx.y, ms.z * mx.z, ms.w * mx.w);
        } else if (CHUNK == 1) {
            const float4* vp = (const float4*)(nrow + 64 + 12 * l);
            float4 va = __ldg(vp), vb = __ldg(vp + 1), vc = __ldg(vp + 2);
            float t0 = (va.x * ev0 + va.y * ev1 + va.z * ev2) * IS3;
            float t1 = (va.w * ev0 + vb.x * ev1 + vb.y * ev2) * IS3;
            float t2 = (vb.z * ev0 + vb.w * ev1 + vc.x * ev2) * IS3;
            float t3 = (vc.y * ev0 + vc.z * ev1 + vc.w * ev2) * IS3;
            if (evalid)
                red4(orow + 64 + 4 * l, t0 * mx.x, t1 * mx.y, t2 * mx.z, t3 * mx.w);
        } else if (CHUNK == 2) {
            const float4* vp = (const float4*)(nrow + 64 + 12 * l);
            float4 va = __ldg(vp), vb = __ldg(vp + 1), vc = __ldg(vp + 2);
            float* po = orow + 128 + 12 * l;
            if (evalid) {
                red4(po,     va.x * mx.x, va.y * mx.x, va.z * mx.x, va.w * mx.y);
                red4(po + 4, vb.x * mx.y, vb.y * mx.y, vb.z * mx.z, vb.w * mx.z);
                red4(po + 8, vc.x * mx.z, vc.y * mx.w, vc.z * mx.w, vc.w * mx.w);
            }
        } else {
            float4 ms = __ldg((const float4*)(nrow + 4 * l));
            float d0 = ms.x * mx.x, d1 = ms.y * mx.y, d2 = ms.z * mx.z, d3 = ms.w * mx.w;
            float* po = orow + 320 + 12 * l;
            if (evalid) {
                red4(po,     d0 * ev0, d0 * ev1, d0 * ev2, d1 * ev0);
                red4(po + 4, d1 * ev1, d1 * ev2, d2 * ev0, d2 * ev1);
                red4(po + 8, d2 * ev2, d3 * ev0, d3 * ev1, d3 * ev2);
            }
        }
    }
}

// ---------------------------------------------------------------------------
// Fused kernel: MLP (chained warp MMAs, fp16 2-term) + coalesced scatter-add.
// Block = 128 threads = 4 warps = 64 edges (16 per warp).
// ---------------------------------------------------------------------------
__global__ void __launch_bounds__(128, 5)
fused_kernel(const float* __restrict__ edge_attrs,
             const float* __restrict__ node_feats,
             const int* __restrict__ senders,
             const int* __restrict__ receivers,
             float* __restrict__ out,
             int n_edges, float act)
{
    __shared__ float smsg[4][16 * MSTRIDE];
    __shared__ int   sh_s[64];
    __shared__ int   sh_r[64];
    __shared__ float sh_ev[64 * 3];

    int tid = threadIdx.x, lane = tid & 31, warp = tid >> 5;
    int g = lane >> 2, t = lane & 3;
    int wbase = blockIdx.x * 64 + warp * 16;
    if (wbase >= n_edges) return;               // whole-warp tail exit
    int e0 = wbase + g, e1 = e0 + 8;
    bool valid0 = e0 < n_edges, valid1 = e1 < n_edges;

    // Each warp loads its own 16 edges' metadata (warp-local, no block sync).
    if (lane < 16) {
        int e = wbase + lane;
        int el = warp * 16 + lane;
        if (e < n_edges) {
            sh_s[el] = __ldg(senders + e);
            sh_r[el] = __ldg(receivers + e);
            const float* ea = edge_attrs + (size_t)e * 11;
            sh_ev[el * 3 + 0] = __ldg(ea + 8);
            sh_ev[el * 3 + 1] = __ldg(ea + 9);
            sh_ev[el * 3 + 2] = __ldg(ea + 10);
        } else {
            sh_s[el] = 0; sh_r[el] = 0;
            sh_ev[el * 3 + 0] = 0.f; sh_ev[el * 3 + 1] = 0.f; sh_ev[el * 3 + 2] = 0.f;
        }
    }
    __syncwarp();

    // ---- Layer 1 A fragments from edge_attrs (K=8, cols 8..15 zero) ----
    float x00 = 0.f, x01 = 0.f, x10 = 0.f, x11 = 0.f;
    if (valid0) {
        const float* p = edge_attrs + (size_t)e0 * 11 + 2 * t;
        x00 = __ldg(p); x01 = __ldg(p + 1);
    }
    if (valid1) {
        const float* p = edge_attrs + (size_t)e1 * 11 + 2 * t;
        x10 = __ldg(p); x11 = __ldg(p + 1);
    }
    uint32_t a0h, a0l, a1h, a1l;
    split2(x00, x01, a0h, a0l);
    split2(x10, x11, a1h, a1l);

    float acc[32];
    uint32_t ah[16], al[16];

    // ---- Layer 1: N=64, single k-tile ----
#pragma unroll
    for (int i = 0; i < 32; i++) acc[i] = 0.f;
#pragma unroll
    for (int nt = 0; nt < 8; nt++) {
        uint2 f = __ldg(&g_wfrag[FRAG_L1 + nt * 32 + lane]);
        float* c = &acc[nt * 4];
        mma16816(c, a0h, a1h, 0u, 0u, f.x, f.y);
        mma16816(c, a0l, a1l, 0u, 0u, f.x, f.y);
    }
    act_split(acc, ah, al, act);

    // ---- Layer 2: 64x64 ----
#pragma unroll
    for (int i = 0; i < 32; i++) acc[i] = 0.f;
#pragma unroll
    for (int nt = 0; nt < 8; nt++) {
#pragma unroll
        for (int kt = 0; kt < 4; kt++) {
            uint2 f = __ldg(&g_wfrag[FRAG_L2 + (nt * 4 + kt) * 32 + lane]);
            float* c = &acc[nt * 4];
            const uint32_t* A = &ah[kt * 4];
            const uint32_t* L = &al[kt * 4];
            mma16816(c, A[0], A[1], A[2], A[3], f.x, f.y);
            mma16816(c, L[0], L[1], L[2], L[3], f.x, f.y);
        }
    }
    act_split(acc, ah, al, act);

    // ---- Layer 3: 64x64 ----
#pragma unroll
    for (int i = 0; i < 32; i++) acc[i] = 0.f;
#pragma unroll
    for (int nt = 0; nt < 8; nt++) {
#pragma unroll
        for (int kt = 0; kt < 4; kt++) {
            uint2 f = __ldg(&g_wfrag[FRAG_L3 + (nt * 4 + kt) * 32 + lane]);
            float* c = &acc[nt * 4];
            const uint32_t* A = &ah[kt * 4];
            const uint32_t* L = &al[kt * 4];
            mma16816(c, A[0], A[1], A[2], A[3], f.x, f.y);
            mma16816(c, L[0], L[1], L[2], L[3], f.x, f.y);
        }
    }
    act_split(acc, ah, al, act);

    // ---- Layer 4 chunks: MMA + staged coalesced scatter, warp-independent ----
    float* wmsg = smsg[warp];
    const int*   ws  = sh_s  + warp * 16;
    const int*   wr  = sh_r  + warp * 16;
    const float* wev = sh_ev + warp * 48;
    int edges_left = n_edges - wbase;
    process_chunk<0>(ah, al, lane, t, g, wmsg, ws, wr, wev, edges_left, node_feats, out);
    process_chunk<1>(ah, al, lane, t, g, wmsg, ws, wr, wev, edges_left, node_feats, out);
    process_chunk<2>(ah, al, lane, t, g, wmsg, ws, wr, wev, edges_left, node_feats, out);
    process_chunk<3>(ah, al, lane, t, g, wmsg, ws, wr, wev, edges_left, node_feats, out);
}

// ---------------------------------------------------------------------------
// Host
// ---------------------------------------------------------------------------
static float compute_act_cst() {
    const int    N = 20000;
    const double a = -14.0, b = 14.0;
    const double h = (b - a) / N;
    double sum = 0.0;
    for (int i = 0; i <= N; i++) {
        double xx  = a + h * i;
        double sig = 1.0 / (1.0 + exp(-xx));
        double sl  = xx * sig;
        double f   = exp(-0.5 * xx * xx) * sl * sl;
        double wq  = (i == 0 || i == N) ? 1.0 : ((i & 1) ? 4.0 : 2.0);
        sum += wq * f;
    }
    sum *= h / 3.0;
    sum /= sqrt(2.0 * M_PI);
    return (float)(1.0 / sqrt(sum));
}

extern "C" void kernel_launch(void* const* d_in, const int* in_sizes, int n_in,
                              void* d_out, int out_size)
{
    const float* node_feats = (const float*)d_in[0];
    const float* edge_attrs = (const float*)d_in[1];
    const int*   senders    = (const int*)d_in[2];
    const int*   receivers  = (const int*)d_in[3];
    const float* w0         = (const float*)d_in[4];
    const float* w1         = (const float*)d_in[5];
    const float* w2         = (const float*)d_in[6];
    const float* w3         = (const float*)d_in[7];
    float*       out        = (float*)d_out;

    int n_edges = in_sizes[2];
    if (n_edges > MAX_EDGES) n_edges = MAX_EDGES;

    float act = compute_act_cst();

    cudaMemsetAsync(d_out, 0, (size_t)out_size * sizeof(float));

    build_frags<<<(FRAG_TOTAL + 255) / 256, 256>>>(w0, w1, w2, w3);

    int blocks = (n_edges + 63) / 64;
    fused_kernel<<<blocks, 128>>>(edge_attrs, node_feats, senders,
                                  receivers, out, n_edges, act);
}